// round 7
// baseline (speedup 1.0000x reference)
#include <cuda_runtime.h>
#include <math.h>

#define NQ 512
#define NC 65536
#define DIN 768

// Scratch (static device globals).
// Corpus: hi-plane rows 0..63 (tf32-valued), row 64 = yn
__device__ float g_cfeatT[65 * NC];
__device__ float g_cfeatLo[64 * NC];
// Query: hi rows 0..63, 64 xn, 65 beta, 66 w0, 67 w1*ln2^2, 68 w2
__device__ float g_qfeatT[69 * NQ];
__device__ float g_qfeatLo[64 * NQ];
// Hidden relu layer for weight MLP
__device__ float g_qy[NQ * 32];

// ---------------- helpers ----------------
__device__ __forceinline__ float f_rcp(float x)  { float r; asm("rcp.approx.f32 %0,%1;"  : "=f"(r) : "f"(x)); return r; }
__device__ __forceinline__ float f_sqrt(float x) { float r; asm("sqrt.approx.f32 %0,%1;" : "=f"(r) : "f"(x)); return r; }
__device__ __forceinline__ float f_lg2(float x)  { float r; asm("lg2.approx.f32 %0,%1;"  : "=f"(r) : "f"(x)); return r; }
__device__ __forceinline__ float tf32_rna(float x) {
    unsigned u; asm("cvt.rna.tf32.f32 %0,%1;" : "=r"(u) : "f"(x)); return __uint_as_float(u);
}
__device__ __forceinline__ void mma_tf32(float c[4], const unsigned a[4], const unsigned b[2]) {
    asm volatile(
        "mma.sync.aligned.m16n8k8.row.col.f32.tf32.tf32.f32 "
        "{%0,%1,%2,%3},{%4,%5,%6,%7},{%8,%9},{%0,%1,%2,%3};"
        : "+f"(c[0]), "+f"(c[1]), "+f"(c[2]), "+f"(c[3])
        : "r"(a[0]), "r"(a[1]), "r"(a[2]), "r"(a[3]), "r"(b[0]), "r"(b[1]));
}
#define QUAD_SUM(x) { x += __shfl_xor_sync(0xffffffffu, x, 1); \
                      x += __shfl_xor_sync(0xffffffffu, x, 2); }

// ---------------------------------------------------------------------------
// Projection (tf32 MMA v2): 128 rows x 64 dims per CTA, 8 warps (one m16 each)
// No psm buffer: epilogue via quad shuffles on the fragment layout.
// Conflict-free smem strides (136 / 72 == 8 mod 32).
// ---------------------------------------------------------------------------
__global__ __launch_bounds__(256, 2) void projmma_kernel(
    const float* __restrict__ X,
    const float* __restrict__ We, const float* __restrict__ be,
    const float* __restrict__ Wh, const float* __restrict__ bh,
    const float* __restrict__ Ws, const float* __restrict__ bs,
    const float* __restrict__ scale_p,
    float* __restrict__ featT, float* __restrict__ featLo,
    int fstride, int is_query)
{
    __shared__ __align__(16) float xsh[16][136];
    __shared__ __align__(16) float xsl[16][136];
    __shared__ __align__(16) float wsh[16][72];
    __shared__ __align__(16) float wsl[16][72];

    const int tid  = threadIdx.x;
    const int lane = tid & 31;
    const int warp = tid >> 5;
    const int gid  = lane >> 2;
    const int tig  = lane & 3;
    const int row0 = blockIdx.x * 128;

    const int rA = tid >> 2;            // 0..63
    const int k4 = (tid & 3) * 4;       // 0,4,8,12
    const float* Xp0 = X + (size_t)(row0 + rA) * DIN + k4;
    const float* Xp1 = X + (size_t)(row0 + rA + 64) * DIN + k4;
    const float* Wp;
    if (rA < 32)      Wp = We + rA * DIN + k4;
    else if (rA < 48) Wp = Wh + (rA - 32) * DIN + k4;
    else              Wp = Ws + (rA - 48) * DIN + k4;

    float4 xv0 = *(const float4*)(Xp0);
    float4 xv1 = *(const float4*)(Xp1);
    float4 wv  = *(const float4*)(Wp);

    float acc[8][4];
#pragma unroll
    for (int t = 0; t < 8; t++)
#pragma unroll
        for (int m = 0; m < 4; m++) acc[t][m] = 0.f;

    for (int k0 = 0; k0 < DIN; k0 += 16) {
        __syncthreads();
        {
            const float* p0 = (const float*)&xv0;
            const float* p1 = (const float*)&xv1;
            const float* pw = (const float*)&wv;
#pragma unroll
            for (int u = 0; u < 4; u++) {
                float h0 = tf32_rna(p0[u]);
                float h1 = tf32_rna(p1[u]);
                float hw = tf32_rna(pw[u]);
                xsh[k4 + u][rA]      = h0;
                xsl[k4 + u][rA]      = tf32_rna(p0[u] - h0);
                xsh[k4 + u][rA + 64] = h1;
                xsl[k4 + u][rA + 64] = tf32_rna(p1[u] - h1);
                wsh[k4 + u][rA]      = hw;
                wsl[k4 + u][rA]      = tf32_rna(pw[u] - hw);
            }
        }
        __syncthreads();
        if (k0 + 16 < DIN) {
            xv0 = *(const float4*)(Xp0 + k0 + 16);
            xv1 = *(const float4*)(Xp1 + k0 + 16);
            wv  = *(const float4*)(Wp  + k0 + 16);
        }
#pragma unroll
        for (int kc = 0; kc < 2; kc++) {
            const int ks = kc * 8;
            const int r = warp * 16 + gid;
            unsigned ah[4], al[4];
            ah[0] = __float_as_uint(xsh[ks + tig][r]);
            ah[1] = __float_as_uint(xsh[ks + tig][r + 8]);
            ah[2] = __float_as_uint(xsh[ks + tig + 4][r]);
            ah[3] = __float_as_uint(xsh[ks + tig + 4][r + 8]);
            al[0] = __float_as_uint(xsl[ks + tig][r]);
            al[1] = __float_as_uint(xsl[ks + tig][r + 8]);
            al[2] = __float_as_uint(xsl[ks + tig + 4][r]);
            al[3] = __float_as_uint(xsl[ks + tig + 4][r + 8]);
#pragma unroll
            for (int ct = 0; ct < 8; ct++) {
                const int cc = ct * 8 + gid;
                unsigned bh2[2], bl2[2];
                bh2[0] = __float_as_uint(wsh[ks + tig][cc]);
                bh2[1] = __float_as_uint(wsh[ks + tig + 4][cc]);
                bl2[0] = __float_as_uint(wsl[ks + tig][cc]);
                bl2[1] = __float_as_uint(wsl[ks + tig + 4][cc]);
                mma_tf32(acc[ct], ah, bh2);
                mma_tf32(acc[ct], ah, bl2);
                mma_tf32(acc[ct], al, bh2);
            }
        }
    }

    // ------------- epilogue: bias + quad-shuffle norms, no smem -------------
    const float sc = *scale_p;
    // add bias (and h-scale) in place
#pragma unroll
    for (int ct = 0; ct < 8; ct++) {
#pragma unroll
        for (int u = 0; u < 2; u++) {
            const int d = ct * 8 + 2 * tig + u;
            float b = (d < 32) ? __ldg(be + d)
                    : (d < 48) ? __ldg(bh + d - 32)
                               : __ldg(bs + d - 48);
            float vA = acc[ct][u]     + b;
            float vB = acc[ct][2 + u] + b;
            if (d >= 32 && d < 48) { vA *= sc; vB *= sc; }
            acc[ct][u]     = vA;
            acc[ct][2 + u] = vB;
        }
    }
    // segment sums
    float s2A = 0.f, s2B = 0.f, h2A = 0.f, h2B = 0.f, s3A = 0.f, s3B = 0.f;
#pragma unroll
    for (int ct = 0; ct < 4; ct++) {
        s2A = fmaf(acc[ct][0], acc[ct][0], s2A); s2A = fmaf(acc[ct][1], acc[ct][1], s2A);
        s2B = fmaf(acc[ct][2], acc[ct][2], s2B); s2B = fmaf(acc[ct][3], acc[ct][3], s2B);
    }
#pragma unroll
    for (int ct = 4; ct < 6; ct++) {
        h2A = fmaf(acc[ct][0], acc[ct][0], h2A); h2A = fmaf(acc[ct][1], acc[ct][1], h2A);
        h2B = fmaf(acc[ct][2], acc[ct][2], h2B); h2B = fmaf(acc[ct][3], acc[ct][3], h2B);
    }
#pragma unroll
    for (int ct = 6; ct < 8; ct++) {
        s3A = fmaf(acc[ct][0], acc[ct][0], s3A); s3A = fmaf(acc[ct][1], acc[ct][1], s3A);
        s3B = fmaf(acc[ct][2], acc[ct][2], s3B); s3B = fmaf(acc[ct][3], acc[ct][3], s3B);
    }
    QUAD_SUM(s2A); QUAD_SUM(s2B);
    QUAD_SUM(h2A); QUAD_SUM(h2B);
    QUAD_SUM(s3A); QUAD_SUM(s3B);

    const float invEA = 1.0f / sqrtf(s2A);
    const float invEB = 1.0f / sqrtf(s2B);
    const float invSA = 1.0f / sqrtf(s3A);
    const float invSB = 1.0f / sqrtf(s3B);
    const float nA = fmaxf(sqrtf(h2A), 1e-15f);
    const float nB = fmaxf(sqrtf(h2B), 1e-15f);
    const float thA = tanhf(nA), thB = tanhf(nB);
    const float facA = thA / nA, facB = thB / nB;

    const int rowA = row0 + warp * 16 + gid;
    const int rowB = rowA + 8;

    // write feature planes (hi/lo split), scattered scalar stores
#pragma unroll
    for (int ct = 0; ct < 8; ct++) {
#pragma unroll
        for (int u = 0; u < 2; u++) {
            const int d = ct * 8 + 2 * tig + u;
            const float fA = (d < 32) ? invEA : (d < 48) ? facA : invSA;
            const float fB = (d < 32) ? invEB : (d < 48) ? facB : invSB;
            float vA = acc[ct][u] * fA;
            float vB = acc[ct][2 + u] * fB;
            float hiA = tf32_rna(vA), hiB = tf32_rna(vB);
            float loA = tf32_rna(vA - hiA), loB = tf32_rna(vB - hiB);
            float* pT = featT  + (size_t)d * fstride;
            float* pL = featLo + (size_t)d * fstride;
            pT[rowA] = hiA; pT[rowB] = hiB;
            pL[rowA] = loA; pL[rowB] = loB;
        }
    }
    if (tig == 0) {
        featT[(size_t)64 * fstride + rowA] = thA * thA;
        featT[(size_t)64 * fstride + rowB] = thB * thB;
        if (is_query) {
            featT[(size_t)65 * fstride + rowA] = 1.0f - thA * thA;
            featT[(size_t)65 * fstride + rowB] = 1.0f - thB * thB;
        }
    }
}

// ---------------------------------------------------------------------------
// Weight-MLP layer 1: relu(x_q @ W1.T + b1) -> g_qy [512][32]
// ---------------------------------------------------------------------------
__global__ __launch_bounds__(256) void mlp32_kernel(
    const float* __restrict__ X, const float* __restrict__ W1,
    const float* __restrict__ b1, float* __restrict__ Y)
{
    __shared__ __align__(16) float xs[16][68];
    __shared__ __align__(16) float ws[16][36];
    const int tid = threadIdx.x;
    const int r0 = (tid >> 3) * 2;
    const int d0 = (tid & 7) * 4;
    const int row0 = blockIdx.x * 64;
    const int lr = tid >> 2;
    const int lk = (tid & 3) * 4;

    float acc[2][4] = {};
    for (int k0 = 0; k0 < DIN; k0 += 16) {
        float4 xv = *(const float4*)(X + (size_t)(row0 + lr) * DIN + k0 + lk);
        float4 wv = make_float4(0.f, 0.f, 0.f, 0.f);
        if (tid < 128) wv = *(const float4*)(W1 + lr * DIN + k0 + lk);
        __syncthreads();
        xs[lk + 0][lr] = xv.x; xs[lk + 1][lr] = xv.y;
        xs[lk + 2][lr] = xv.z; xs[lk + 3][lr] = xv.w;
        if (tid < 128) {
            ws[lk + 0][lr] = wv.x; ws[lk + 1][lr] = wv.y;
            ws[lk + 2][lr] = wv.z; ws[lk + 3][lr] = wv.w;
        }
        __syncthreads();
#pragma unroll
        for (int kk = 0; kk < 16; kk++) {
            float a0 = xs[kk][r0];
            float a1 = xs[kk][r0 + 1];
            float4 b4 = *(const float4*)&ws[kk][d0];
            float bv[4] = {b4.x, b4.y, b4.z, b4.w};
#pragma unroll
            for (int j = 0; j < 4; j++) {
                acc[0][j] = fmaf(a0, bv[j], acc[0][j]);
                acc[1][j] = fmaf(a1, bv[j], acc[1][j]);
            }
        }
    }
#pragma unroll
    for (int i = 0; i < 2; i++)
#pragma unroll
        for (int j = 0; j < 4; j++)
            Y[(size_t)(row0 + r0 + i) * 32 + d0 + j] =
                fmaxf(acc[i][j] + b1[d0 + j], 0.f);
}

// ---------------------------------------------------------------------------
// Weight-MLP layer 2 + softplus -> g_qfeatT rows 66..68 (w1 scaled by ln2^2)
// ---------------------------------------------------------------------------
__global__ void wmlp_kernel(const float* __restrict__ Y,
                            const float* __restrict__ W2,
                            const float* __restrict__ b2,
                            float* __restrict__ qfT)
{
    int q = blockIdx.x * blockDim.x + threadIdx.x;
    if (q >= NQ) return;
    float z0 = b2[0], z1 = b2[1], z2 = b2[2];
#pragma unroll
    for (int k = 0; k < 32; k++) {
        float y = Y[q * 32 + k];
        z0 = fmaf(y, W2[k],      z0);
        z1 = fmaf(y, W2[32 + k], z1);
        z2 = fmaf(y, W2[64 + k], z2);
    }
    float sp0 = fmaxf(z0, 0.f) + log1pf(expf(-fabsf(z0)));
    float sp1 = fmaxf(z1, 0.f) + log1pf(expf(-fabsf(z1)));
    float sp2 = fmaxf(z2, 0.f) + log1pf(expf(-fabsf(z2)));
    qfT[(size_t)66 * NQ + q] = sp0;
    qfT[(size_t)67 * NQ + q] = sp1 * 0.4804530139182014f;  // fold ln2^2
    qfT[(size_t)68 * NQ + q] = sp2;
}

// ---------------------------------------------------------------------------
// Pairwise kernel: 64q x 128c per CTA, 8 warps of 32x32, tf32 MMA split hi/lo
// Conflict-free smem strides (72 / 136).
// ---------------------------------------------------------------------------
__global__ __launch_bounds__(256, 2) void pair_kernel(
    const float* __restrict__ qfT, const float* __restrict__ qfLo,
    const float* __restrict__ cfT, const float* __restrict__ cfLo,
    float* __restrict__ out)
{
    __shared__ __align__(16) float sqh[16][72], sql[16][72];
    __shared__ __align__(16) float sch[16][136], sclo[16][136];
    __shared__ float qxn[64], qbt[64], qw0[64], qw1[64], qw2[64], cyn[128];

    const int tid  = threadIdx.x;
    const int lane = tid & 31;
    const int warp = tid >> 5;
    const int gid  = lane >> 2;
    const int tig  = lane & 3;
    const int qw   = (warp >> 2) * 32;
    const int cw   = (warp & 3) * 32;

    const int q0 = blockIdx.y * 64;
    const int c0 = blockIdx.x * 128;

    if (tid < 64) {
        qxn[tid] = qfT[(size_t)64 * NQ + q0 + tid];
        qbt[tid] = qfT[(size_t)65 * NQ + q0 + tid];
        qw0[tid] = qfT[(size_t)66 * NQ + q0 + tid];
        qw1[tid] = qfT[(size_t)67 * NQ + q0 + tid];
        qw2[tid] = qfT[(size_t)68 * NQ + q0 + tid];
    } else if (tid < 192) {
        const int r = tid - 64;
        cyn[r] = cfT[(size_t)64 * NC + c0 + r];
    }

    auto stage = [&](int off) {
        {
            const int row = tid >> 4;
            const int c4  = (tid & 15) * 4;
            *(float4*)&sqh[row][c4] = *(const float4*)(qfT  + (size_t)(off + row) * NQ + q0 + c4);
            *(float4*)&sql[row][c4] = *(const float4*)(qfLo + (size_t)(off + row) * NQ + q0 + c4);
        }
        for (int t = tid; t < 512; t += 256) {
            const int row = t >> 5;
            const int c4  = (t & 31) * 4;
            *(float4*)&sch [row][c4] = *(const float4*)(cfT  + (size_t)(off + row) * NC + c0 + c4);
            *(float4*)&sclo[row][c4] = *(const float4*)(cfLo + (size_t)(off + row) * NC + c0 + c4);
        }
    };

    auto seg_mma = [&](float acc[8][4]) {
#pragma unroll
        for (int kc = 0; kc < 2; kc++) {
            const int k0 = kc * 8;
            unsigned bh[4][2], bl[4][2];
#pragma unroll
            for (int ct = 0; ct < 4; ct++) {
                const int cc = cw + ct * 8 + gid;
                bh[ct][0] = __float_as_uint(sch [k0 + tig][cc]);
                bh[ct][1] = __float_as_uint(sch [k0 + tig + 4][cc]);
                bl[ct][0] = __float_as_uint(sclo[k0 + tig][cc]);
                bl[ct][1] = __float_as_uint(sclo[k0 + tig + 4][cc]);
            }
#pragma unroll
            for (int qt = 0; qt < 2; qt++) {
                const int r = qw + qt * 16 + gid;
                unsigned ah[4], al[4];
                ah[0] = __float_as_uint(sqh[k0 + tig][r]);
                ah[1] = __float_as_uint(sqh[k0 + tig][r + 8]);
                ah[2] = __float_as_uint(sqh[k0 + tig + 4][r]);
                ah[3] = __float_as_uint(sqh[k0 + tig + 4][r + 8]);
                al[0] = __float_as_uint(sql[k0 + tig][r]);
                al[1] = __float_as_uint(sql[k0 + tig][r + 8]);
                al[2] = __float_as_uint(sql[k0 + tig + 4][r]);
                al[3] = __float_as_uint(sql[k0 + tig + 4][r + 8]);
#pragma unroll
                for (int ct = 0; ct < 4; ct++) {
                    float* a = acc[qt * 4 + ct];
                    mma_tf32(a, ah, bh[ct]);
                    mma_tf32(a, ah, bl[ct]);
                    mma_tf32(a, al, bh[ct]);
                }
            }
        }
    };

    float tot[8][4];
    float acc[8][4];

    // ================= phase e =================
#pragma unroll
    for (int t = 0; t < 8; t++)
#pragma unroll
        for (int m = 0; m < 4; m++) acc[t][m] = 0.f;
    stage(0);
    __syncthreads();
    seg_mma(acc);
    __syncthreads();
    stage(16);
    __syncthreads();
    seg_mma(acc);
#pragma unroll
    for (int qt = 0; qt < 2; qt++) {
        const int lqA = qw + qt * 16 + gid;
        const float wA = qw0[lqA], wB = qw0[lqA + 8];
#pragma unroll
        for (int ct = 0; ct < 4; ct++) {
            const int t = qt * 4 + ct;
            tot[t][0] = wA * (2.f - 2.f * acc[t][0]);
            tot[t][1] = wA * (2.f - 2.f * acc[t][1]);
            tot[t][2] = wB * (2.f - 2.f * acc[t][2]);
            tot[t][3] = wB * (2.f - 2.f * acc[t][3]);
        }
    }

    // ================= phase h =================
#pragma unroll
    for (int t = 0; t < 8; t++)
#pragma unroll
        for (int m = 0; m < 4; m++) acc[t][m] = 0.f;
    __syncthreads();
    stage(32);
    __syncthreads();
    seg_mma(acc);
#pragma unroll
    for (int qt = 0; qt < 2; qt++) {
        const int lqA = qw + qt * 16 + gid;
#pragma unroll
        for (int half = 0; half < 2; half++) {
            const int lq = lqA + half * 8;
            const float xn = qxn[lq];
            const float bt = qbt[lq];
            const float nb = -2.f * bt;
            const float bb = bt * bt;
            const float w1 = qw1[lq];
#pragma unroll
            for (int ct = 0; ct < 4; ct++) {
                const int t = qt * 4 + ct;
                const int lc = cw + ct * 8 + 2 * tig;
#pragma unroll
                for (int m = 0; m < 2; m++) {
                    const float dh = acc[t][half * 2 + m];
                    const float yn = cyn[lc + m];
                    float s1 = fmaf(-2.f, dh, 1.f);
                    float alpha = s1 + yn;
                    float num = fmaf(alpha, fmaf(alpha, xn, nb * dh), bb * yn);
                    float den = fmaxf(fmaf(xn, yn, s1), 1e-15f);
                    float tv = f_sqrt(fmaxf(num, 0.f)) * f_rcp(den);
                    tv = fminf(tv, 0.99999994f);
                    float L = f_lg2((1.f + tv) * f_rcp(1.f - tv));
                    tot[t][half * 2 + m] = fmaf(w1, L * L, tot[t][half * 2 + m]);
                }
            }
        }
    }

    // ================= phase s =================
#pragma unroll
    for (int t = 0; t < 8; t++)
#pragma unroll
        for (int m = 0; m < 4; m++) acc[t][m] = 0.f;
    __syncthreads();
    stage(48);
    __syncthreads();
    seg_mma(acc);
#pragma unroll
    for (int qt = 0; qt < 2; qt++) {
        const int lqA = qw + qt * 16 + gid;
#pragma unroll
        for (int half = 0; half < 2; half++) {
            const int lq = lqA + half * 8;
            const float w2 = qw2[lq];
#pragma unroll
            for (int ct = 0; ct < 4; ct++) {
                const int t = qt * 4 + ct;
#pragma unroll
                for (int m = 0; m < 2; m++) {
                    const float d = acc[t][half * 2 + m];
                    float ad = fminf(fabsf(d), 1.f);
                    float sq = f_sqrt(fmaxf(1.f - ad, 0.f));
                    float p = -0.0012624911f;
                    p = fmaf(p, ad,  0.0066700901f);
                    p = fmaf(p, ad, -0.0170881256f);
                    p = fmaf(p, ad,  0.0308918810f);
                    p = fmaf(p, ad, -0.0501743046f);
                    p = fmaf(p, ad,  0.0889789874f);
                    p = fmaf(p, ad, -0.2145988016f);
                    p = fmaf(p, ad,  1.5707963050f);
                    float r = sq * p;
                    float a = (d >= 0.f) ? r : 3.14159265358979f - r;
                    tot[t][half * 2 + m] = fmaf(w2, a * a, tot[t][half * 2 + m]);
                }
            }
        }
    }

    // ================= store -total =================
#pragma unroll
    for (int qt = 0; qt < 2; qt++) {
        const int lqA = qw + qt * 16 + gid;
#pragma unroll
        for (int ct = 0; ct < 4; ct++) {
            const int t = qt * 4 + ct;
            const int lc = cw + ct * 8 + 2 * tig;
            float2 oA = make_float2(-tot[t][0], -tot[t][1]);
            float2 oB = make_float2(-tot[t][2], -tot[t][3]);
            *(float2*)(out + (size_t)(q0 + lqA) * NC + c0 + lc)     = oA;
            *(float2*)(out + (size_t)(q0 + lqA + 8) * NC + c0 + lc) = oB;
        }
    }
}

// ---------------------------------------------------------------------------
extern "C" void kernel_launch(void* const* d_in, const int* in_sizes, int n_in,
                              void* d_out, int out_size)
{
    const float* x_q  = (const float*)d_in[0];
    const float* x_c  = (const float*)d_in[1];
    const float* We   = (const float*)d_in[2];
    const float* be   = (const float*)d_in[3];
    const float* Wh   = (const float*)d_in[4];
    const float* bh   = (const float*)d_in[5];
    const float* Ws   = (const float*)d_in[6];
    const float* bs   = (const float*)d_in[7];
    const float* scl  = (const float*)d_in[8];
    const float* W1   = (const float*)d_in[9];
    const float* b1   = (const float*)d_in[10];
    const float* W2   = (const float*)d_in[11];
    const float* b2   = (const float*)d_in[12];
    float* out = (float*)d_out;

    float *cfT, *cfLo, *qfT, *qfLo, *qy;
    cudaGetSymbolAddress((void**)&cfT,  g_cfeatT);
    cudaGetSymbolAddress((void**)&cfLo, g_cfeatLo);
    cudaGetSymbolAddress((void**)&qfT,  g_qfeatT);
    cudaGetSymbolAddress((void**)&qfLo, g_qfeatLo);
    cudaGetSymbolAddress((void**)&qy,   g_qy);

    projmma_kernel<<<NC / 128, 256>>>(x_c, We, be, Wh, bh, Ws, bs, scl, cfT, cfLo, NC, 0);
    projmma_kernel<<<NQ / 128, 256>>>(x_q, We, be, Wh, bh, Ws, bs, scl, qfT, qfLo, NQ, 1);
    mlp32_kernel<<<NQ / 64, 256>>>(x_q, W1, b1, qy);
    wmlp_kernel<<<2, 256>>>(qy, W2, b2, qfT);
    pair_kernel<<<dim3(NC / 128, NQ / 64), 256>>>(qfT, qfLo, cfT, cfLo, out);
}

// round 8
// speedup vs baseline: 1.5660x; 1.5660x over previous
#include <cuda_runtime.h>
#include <math.h>

#define NQ 512
#define NC 65536
#define DIN 768

// Scratch (static device globals).
__device__ float g_cfeatT[65 * NC];    // corpus: rows 0..63 hi, 64 = yn
__device__ float g_cfeatLo[64 * NC];
__device__ float g_qfeatT[69 * NQ];    // query: 0..63 hi, 64 xn, 65 beta, 66 w0, 67 w1*ln2^2, 68 w2
__device__ float g_qfeatLo[64 * NQ];
__device__ float g_wHi[64 * DIN];      // concatenated We/Wh/Ws tf32 hi
__device__ float g_wLo[64 * DIN];      // ... lo residual

// ---------------- helpers ----------------
__device__ __forceinline__ float f_rcp(float x)  { float r; asm("rcp.approx.f32 %0,%1;"  : "=f"(r) : "f"(x)); return r; }
__device__ __forceinline__ float f_sqrt(float x) { float r; asm("sqrt.approx.f32 %0,%1;" : "=f"(r) : "f"(x)); return r; }
__device__ __forceinline__ float f_lg2(float x)  { float r; asm("lg2.approx.f32 %0,%1;"  : "=f"(r) : "f"(x)); return r; }
__device__ __forceinline__ float tf32_rna(float x) {
    unsigned u; asm("cvt.rna.tf32.f32 %0,%1;" : "=r"(u) : "f"(x)); return __uint_as_float(u);
}
__device__ __forceinline__ void mma_tf32(float c[4], const unsigned a[4], const unsigned b[2]) {
    asm volatile(
        "mma.sync.aligned.m16n8k8.row.col.f32.tf32.tf32.f32 "
        "{%0,%1,%2,%3},{%4,%5,%6,%7},{%8,%9},{%0,%1,%2,%3};"
        : "+f"(c[0]), "+f"(c[1]), "+f"(c[2]), "+f"(c[3])
        : "r"(a[0]), "r"(a[1]), "r"(a[2]), "r"(a[3]), "r"(b[0]), "r"(b[1]));
}

// ---------------------------------------------------------------------------
// One-time W split: concatenated [64][768] tf32 hi/lo planes
// ---------------------------------------------------------------------------
__global__ void wsplit_kernel(const float* __restrict__ We,
                              const float* __restrict__ Wh,
                              const float* __restrict__ Ws,
                              float* __restrict__ wHi, float* __restrict__ wLo)
{
    int i = blockIdx.x * 256 + threadIdx.x;
    if (i >= 64 * DIN) return;
    int d = i / DIN;
    int k = i - d * DIN;
    float v = (d < 32) ? We[d * DIN + k]
            : (d < 48) ? Wh[(d - 32) * DIN + k]
                       : Ws[(d - 48) * DIN + k];
    float hi = tf32_rna(v);
    wHi[i] = hi;
    wLo[i] = tf32_rna(v - hi);
}

// ---------------------------------------------------------------------------
// Projection (tf32 MMA v3): 64 rows x 64 dims per CTA, 128 threads (4 warps),
// 4 CTAs/SM. W hi/lo precomputed. Coalesced psm epilogue (aliases staging).
// ---------------------------------------------------------------------------
__global__ __launch_bounds__(128, 4) void projmma_kernel(
    const float* __restrict__ X,
    const float* __restrict__ be, const float* __restrict__ bh,
    const float* __restrict__ bs, const float* __restrict__ scale_p,
    const float* __restrict__ wHi, const float* __restrict__ wLo,
    float* __restrict__ featT, float* __restrict__ featLo,
    int fstride, int is_query)
{
    __shared__ __align__(16) float sbuf[4608];           // 18.4 KB
    float (*xsh)[72] = (float(*)[72])(sbuf);             // 16 x 72
    float (*xsl)[72] = (float(*)[72])(sbuf + 1152);
    float (*wsh)[72] = (float(*)[72])(sbuf + 2304);
    float (*wsl)[72] = (float(*)[72])(sbuf + 3456);
    float (*psm)[69] = (float(*)[69])(sbuf);             // 64 x 69 (aliases)

    const int tid  = threadIdx.x;
    const int lane = tid & 31;
    const int warp = tid >> 5;       // 0..3 -> rows warp*16..
    const int gid  = lane >> 2;
    const int tig  = lane & 3;
    const int row0 = blockIdx.x * 64;

    const int rA = tid >> 1;         // 0..63 (x-row / w-dim)
    const int k8 = (tid & 1) * 8;    // 0 or 8

    const float* Xp  = X   + (size_t)(row0 + rA) * DIN + k8;
    const float* WHp = wHi + rA * DIN + k8;
    const float* WLp = wLo + rA * DIN + k8;

    float4 xv0 = *(const float4*)(Xp);
    float4 xv1 = *(const float4*)(Xp + 4);
    float4 wh0 = *(const float4*)(WHp);
    float4 wh1 = *(const float4*)(WHp + 4);
    float4 wl0 = *(const float4*)(WLp);
    float4 wl1 = *(const float4*)(WLp + 4);

    float acc[8][4];
#pragma unroll
    for (int t = 0; t < 8; t++)
#pragma unroll
        for (int m = 0; m < 4; m++) acc[t][m] = 0.f;

    for (int k0 = 0; k0 < DIN; k0 += 16) {
        __syncthreads();
        {
            const float* p0 = (const float*)&xv0;
            const float* p1 = (const float*)&xv1;
            const float* h0 = (const float*)&wh0;
            const float* h1 = (const float*)&wh1;
            const float* l0 = (const float*)&wl0;
            const float* l1 = (const float*)&wl1;
#pragma unroll
            for (int u = 0; u < 4; u++) {
                float a0 = tf32_rna(p0[u]);
                float a1 = tf32_rna(p1[u]);
                xsh[k8 + u][rA]     = a0;
                xsl[k8 + u][rA]     = tf32_rna(p0[u] - a0);
                xsh[k8 + 4 + u][rA] = a1;
                xsl[k8 + 4 + u][rA] = tf32_rna(p1[u] - a1);
                wsh[k8 + u][rA]     = h0[u];
                wsh[k8 + 4 + u][rA] = h1[u];
                wsl[k8 + u][rA]     = l0[u];
                wsl[k8 + 4 + u][rA] = l1[u];
            }
        }
        __syncthreads();
        if (k0 + 16 < DIN) {
            xv0 = *(const float4*)(Xp  + k0 + 16);
            xv1 = *(const float4*)(Xp  + k0 + 20);
            wh0 = *(const float4*)(WHp + k0 + 16);
            wh1 = *(const float4*)(WHp + k0 + 20);
            wl0 = *(const float4*)(WLp + k0 + 16);
            wl1 = *(const float4*)(WLp + k0 + 20);
        }
#pragma unroll
        for (int kc = 0; kc < 2; kc++) {
            const int ks = kc * 8;
            const int r = warp * 16 + gid;
            unsigned ah[4], al[4];
            ah[0] = __float_as_uint(xsh[ks + tig][r]);
            ah[1] = __float_as_uint(xsh[ks + tig][r + 8]);
            ah[2] = __float_as_uint(xsh[ks + tig + 4][r]);
            ah[3] = __float_as_uint(xsh[ks + tig + 4][r + 8]);
            al[0] = __float_as_uint(xsl[ks + tig][r]);
            al[1] = __float_as_uint(xsl[ks + tig][r + 8]);
            al[2] = __float_as_uint(xsl[ks + tig + 4][r]);
            al[3] = __float_as_uint(xsl[ks + tig + 4][r + 8]);
#pragma unroll
            for (int ct = 0; ct < 8; ct++) {
                const int cc = ct * 8 + gid;
                unsigned bh2[2], bl2[2];
                bh2[0] = __float_as_uint(wsh[ks + tig][cc]);
                bh2[1] = __float_as_uint(wsh[ks + tig + 4][cc]);
                bl2[0] = __float_as_uint(wsl[ks + tig][cc]);
                bl2[1] = __float_as_uint(wsl[ks + tig + 4][cc]);
                mma_tf32(acc[ct], ah, bh2);
                mma_tf32(acc[ct], ah, bl2);
                mma_tf32(acc[ct], al, bh2);
            }
        }
    }

    __syncthreads();   // staging dead; psm aliases it
    {
        const int r = warp * 16 + gid;
#pragma unroll
        for (int ct = 0; ct < 8; ct++) {
#pragma unroll
            for (int u = 0; u < 2; u++) {
                const int d = ct * 8 + 2 * tig + u;
                float bias = (d < 32) ? __ldg(be + d)
                           : (d < 48) ? __ldg(bh + d - 32)
                                      : __ldg(bs + d - 48);
                psm[r][d]     = acc[ct][u]     + bias;
                psm[r + 8][d] = acc[ct][2 + u] + bias;
            }
        }
    }
    __syncthreads();

    if (tid < 64) {
        const int r = tid;
        const float sc = *scale_p;
        float s2 = 0.f;
#pragma unroll
        for (int k = 0; k < 32; k++) { float v = psm[r][k]; s2 = fmaf(v, v, s2); }
        float inv = 1.0f / sqrtf(s2);
#pragma unroll
        for (int k = 0; k < 32; k++) psm[r][k] *= inv;
        float h2 = 0.f;
#pragma unroll
        for (int k = 32; k < 48; k++) { float v = psm[r][k] * sc; psm[r][k] = v; h2 = fmaf(v, v, h2); }
        float n  = fmaxf(sqrtf(h2), 1e-15f);
        float th = tanhf(n);
        float fac = th / n;
#pragma unroll
        for (int k = 32; k < 48; k++) psm[r][k] *= fac;
        psm[r][64] = th * th;                       // yn / xn
        if (is_query) psm[r][65] = 1.0f - th * th;  // beta
        float s3 = 0.f;
#pragma unroll
        for (int k = 48; k < 64; k++) { float v = psm[r][k]; s3 = fmaf(v, v, s3); }
        float inv3 = 1.0f / sqrtf(s3);
#pragma unroll
        for (int k = 48; k < 64; k++) psm[r][k] *= inv3;
    }
    __syncthreads();

    // features: hi/lo split, coalesced (64-wide rows)
    for (int i = tid; i < 64 * 64; i += 128) {
        int k = i >> 6, r = i & 63;
        float v = psm[r][k];
        float hi = tf32_rna(v);
        float lo = tf32_rna(v - hi);
        featT [(size_t)k * fstride + row0 + r] = hi;
        featLo[(size_t)k * fstride + row0 + r] = lo;
    }
    const int np = is_query ? 2 : 1;
    for (int i = tid; i < np * 64; i += 128) {
        int k = 64 + (i >> 6), r = i & 63;
        featT[(size_t)k * fstride + row0 + r] = psm[r][k];
    }
}

// ---------------------------------------------------------------------------
// Fused weight MLP: relu(x_q W1^T + b1) -> (W2, b2) -> softplus -> qfT 66..68
// ---------------------------------------------------------------------------
__global__ __launch_bounds__(256) void mlpq_kernel(
    const float* __restrict__ X, const float* __restrict__ W1,
    const float* __restrict__ b1, const float* __restrict__ W2,
    const float* __restrict__ b2, float* __restrict__ qfT)
{
    __shared__ __align__(16) float xs[16][68];
    __shared__ __align__(16) float ws[16][36];
    __shared__ __align__(16) float ys[64][33];
    const int tid = threadIdx.x;
    const int r0 = (tid >> 3) * 2;
    const int d0 = (tid & 7) * 4;
    const int row0 = blockIdx.x * 64;
    const int lr = tid >> 2;
    const int lk = (tid & 3) * 4;

    float acc[2][4] = {};
    for (int k0 = 0; k0 < DIN; k0 += 16) {
        float4 xv = *(const float4*)(X + (size_t)(row0 + lr) * DIN + k0 + lk);
        float4 wv = make_float4(0.f, 0.f, 0.f, 0.f);
        if (tid < 128) wv = *(const float4*)(W1 + lr * DIN + k0 + lk);
        __syncthreads();
        xs[lk + 0][lr] = xv.x; xs[lk + 1][lr] = xv.y;
        xs[lk + 2][lr] = xv.z; xs[lk + 3][lr] = xv.w;
        if (tid < 128) {
            ws[lk + 0][lr] = wv.x; ws[lk + 1][lr] = wv.y;
            ws[lk + 2][lr] = wv.z; ws[lk + 3][lr] = wv.w;
        }
        __syncthreads();
#pragma unroll
        for (int kk = 0; kk < 16; kk++) {
            float a0 = xs[kk][r0];
            float a1 = xs[kk][r0 + 1];
            float4 b4 = *(const float4*)&ws[kk][d0];
            float bv[4] = {b4.x, b4.y, b4.z, b4.w};
#pragma unroll
            for (int j = 0; j < 4; j++) {
                acc[0][j] = fmaf(a0, bv[j], acc[0][j]);
                acc[1][j] = fmaf(a1, bv[j], acc[1][j]);
            }
        }
    }
#pragma unroll
    for (int i = 0; i < 2; i++)
#pragma unroll
        for (int j = 0; j < 4; j++)
            ys[r0 + i][d0 + j] = fmaxf(acc[i][j] + b1[d0 + j], 0.f);
    __syncthreads();

    if (tid < 64) {
        const int q = row0 + tid;
        float z0 = b2[0], z1 = b2[1], z2 = b2[2];
#pragma unroll
        for (int k = 0; k < 32; k++) {
            float y = ys[tid][k];
            z0 = fmaf(y, __ldg(W2 + k),      z0);
            z1 = fmaf(y, __ldg(W2 + 32 + k), z1);
            z2 = fmaf(y, __ldg(W2 + 64 + k), z2);
        }
        float sp0 = fmaxf(z0, 0.f) + log1pf(expf(-fabsf(z0)));
        float sp1 = fmaxf(z1, 0.f) + log1pf(expf(-fabsf(z1)));
        float sp2 = fmaxf(z2, 0.f) + log1pf(expf(-fabsf(z2)));
        qfT[(size_t)66 * NQ + q] = sp0;
        qfT[(size_t)67 * NQ + q] = sp1 * 0.4804530139182014f;  // fold ln2^2
        qfT[(size_t)68 * NQ + q] = sp2;
    }
}

// ---------------------------------------------------------------------------
// Pairwise kernel: 64q x 128c per CTA, 8 warps of 32x32, tf32 MMA split hi/lo
// (round-5 structure; conflict-free pads 72 / 136)
// ---------------------------------------------------------------------------
__global__ __launch_bounds__(256, 2) void pair_kernel(
    const float* __restrict__ qfT, const float* __restrict__ qfLo,
    const float* __restrict__ cfT, const float* __restrict__ cfLo,
    float* __restrict__ out)
{
    __shared__ __align__(16) float sqh[16][72], sql[16][72];
    __shared__ __align__(16) float sch[16][136], sclo[16][136];
    __shared__ float qxn[64], qbt[64], qw0[64], qw1[64], qw2[64], cyn[128];

    const int tid  = threadIdx.x;
    const int lane = tid & 31;
    const int warp = tid >> 5;
    const int gid  = lane >> 2;
    const int tig  = lane & 3;
    const int qw   = (warp >> 2) * 32;
    const int cw   = (warp & 3) * 32;

    const int q0 = blockIdx.y * 64;
    const int c0 = blockIdx.x * 128;

    if (tid < 64) {
        qxn[tid] = qfT[(size_t)64 * NQ + q0 + tid];
        qbt[tid] = qfT[(size_t)65 * NQ + q0 + tid];
        qw0[tid] = qfT[(size_t)66 * NQ + q0 + tid];
        qw1[tid] = qfT[(size_t)67 * NQ + q0 + tid];
        qw2[tid] = qfT[(size_t)68 * NQ + q0 + tid];
    } else if (tid < 192) {
        const int r = tid - 64;
        cyn[r] = cfT[(size_t)64 * NC + c0 + r];
    }

    auto stage = [&](int off) {
        {
            const int row = tid >> 4;
            const int c4  = (tid & 15) * 4;
            *(float4*)&sqh[row][c4] = *(const float4*)(qfT  + (size_t)(off + row) * NQ + q0 + c4);
            *(float4*)&sql[row][c4] = *(const float4*)(qfLo + (size_t)(off + row) * NQ + q0 + c4);
        }
        for (int t = tid; t < 512; t += 256) {
            const int row = t >> 5;
            const int c4  = (t & 31) * 4;
            *(float4*)&sch [row][c4] = *(const float4*)(cfT  + (size_t)(off + row) * NC + c0 + c4);
            *(float4*)&sclo[row][c4] = *(const float4*)(cfLo + (size_t)(off + row) * NC + c0 + c4);
        }
    };

    auto seg_mma = [&](float acc[8][4]) {
#pragma unroll
        for (int kc = 0; kc < 2; kc++) {
            const int k0 = kc * 8;
            unsigned bh[4][2], bl[4][2];
#pragma unroll
            for (int ct = 0; ct < 4; ct++) {
                const int cc = cw + ct * 8 + gid;
                bh[ct][0] = __float_as_uint(sch [k0 + tig][cc]);
                bh[ct][1] = __float_as_uint(sch [k0 + tig + 4][cc]);
                bl[ct][0] = __float_as_uint(sclo[k0 + tig][cc]);
                bl[ct][1] = __float_as_uint(sclo[k0 + tig + 4][cc]);
            }
#pragma unroll
            for (int qt = 0; qt < 2; qt++) {
                const int r = qw + qt * 16 + gid;
                unsigned ah[4], al[4];
                ah[0] = __float_as_uint(sqh[k0 + tig][r]);
                ah[1] = __float_as_uint(sqh[k0 + tig][r + 8]);
                ah[2] = __float_as_uint(sqh[k0 + tig + 4][r]);
                ah[3] = __float_as_uint(sqh[k0 + tig + 4][r + 8]);
                al[0] = __float_as_uint(sql[k0 + tig][r]);
                al[1] = __float_as_uint(sql[k0 + tig][r + 8]);
                al[2] = __float_as_uint(sql[k0 + tig + 4][r]);
                al[3] = __float_as_uint(sql[k0 + tig + 4][r + 8]);
#pragma unroll
                for (int ct = 0; ct < 4; ct++) {
                    float* a = acc[qt * 4 + ct];
                    mma_tf32(a, ah, bh[ct]);
                    mma_tf32(a, ah, bl[ct]);
                    mma_tf32(a, al, bh[ct]);
                }
            }
        }
    };

    float tot[8][4];
    float acc[8][4];

    // ================= phase e =================
#pragma unroll
    for (int t = 0; t < 8; t++)
#pragma unroll
        for (int m = 0; m < 4; m++) acc[t][m] = 0.f;
    stage(0);
    __syncthreads();
    seg_mma(acc);
    __syncthreads();
    stage(16);
    __syncthreads();
    seg_mma(acc);
#pragma unroll
    for (int qt = 0; qt < 2; qt++) {
        const int lqA = qw + qt * 16 + gid;
        const float wA = qw0[lqA], wB = qw0[lqA + 8];
#pragma unroll
        for (int ct = 0; ct < 4; ct++) {
            const int t = qt * 4 + ct;
            tot[t][0] = wA * (2.f - 2.f * acc[t][0]);
            tot[t][1] = wA * (2.f - 2.f * acc[t][1]);
            tot[t][2] = wB * (2.f - 2.f * acc[t][2]);
            tot[t][3] = wB * (2.f - 2.f * acc[t][3]);
        }
    }

    // ================= phase h =================
#pragma unroll
    for (int t = 0; t < 8; t++)
#pragma unroll
        for (int m = 0; m < 4; m++) acc[t][m] = 0.f;
    __syncthreads();
    stage(32);
    __syncthreads();
    seg_mma(acc);
#pragma unroll
    for (int qt = 0; qt < 2; qt++) {
        const int lqA = qw + qt * 16 + gid;
#pragma unroll
        for (int half = 0; half < 2; half++) {
            const int lq = lqA + half * 8;
            const float xn = qxn[lq];
            const float bt = qbt[lq];
            const float nb = -2.f * bt;
            const float bb = bt * bt;
            const float w1 = qw1[lq];
#pragma unroll
            for (int ct = 0; ct < 4; ct++) {
                const int t = qt * 4 + ct;
                const int lc = cw + ct * 8 + 2 * tig;
#pragma unroll
                for (int m = 0; m < 2; m++) {
                    const float dh = acc[t][half * 2 + m];
                    const float yn = cyn[lc + m];
                    float s1 = fmaf(-2.f, dh, 1.f);
                    float alpha = s1 + yn;
                    float num = fmaf(alpha, fmaf(alpha, xn, nb * dh), bb * yn);
                    float den = fmaxf(fmaf(xn, yn, s1), 1e-15f);
                    float tv = f_sqrt(fmaxf(num, 0.f)) * f_rcp(den);
                    tv = fminf(tv, 0.99999994f);
                    float L = f_lg2((1.f + tv) * f_rcp(1.f - tv));
                    tot[t][half * 2 + m] = fmaf(w1, L * L, tot[t][half * 2 + m]);
                }
            }
        }
    }

    // ================= phase s =================
#pragma unroll
    for (int t = 0; t < 8; t++)
#pragma unroll
        for (int m = 0; m < 4; m++) acc[t][m] = 0.f;
    __syncthreads();
    stage(48);
    __syncthreads();
    seg_mma(acc);
#pragma unroll
    for (int qt = 0; qt < 2; qt++) {
        const int lqA = qw + qt * 16 + gid;
#pragma unroll
        for (int half = 0; half < 2; half++) {
            const int lq = lqA + half * 8;
            const float w2 = qw2[lq];
#pragma unroll
            for (int ct = 0; ct < 4; ct++) {
                const int t = qt * 4 + ct;
#pragma unroll
                for (int m = 0; m < 2; m++) {
                    const float d = acc[t][half * 2 + m];
                    float ad = fminf(fabsf(d), 1.f);
                    float sq = f_sqrt(fmaxf(1.f - ad, 0.f));
                    float p = -0.0012624911f;
                    p = fmaf(p, ad,  0.0066700901f);
                    p = fmaf(p, ad, -0.0170881256f);
                    p = fmaf(p, ad,  0.0308918810f);
                    p = fmaf(p, ad, -0.0501743046f);
                    p = fmaf(p, ad,  0.0889789874f);
                    p = fmaf(p, ad, -0.2145988016f);
                    p = fmaf(p, ad,  1.5707963050f);
                    float r = sq * p;
                    float a = (d >= 0.f) ? r : 3.14159265358979f - r;
                    tot[t][half * 2 + m] = fmaf(w2, a * a, tot[t][half * 2 + m]);
                }
            }
        }
    }

    // ================= store -total =================
#pragma unroll
    for (int qt = 0; qt < 2; qt++) {
        const int lqA = qw + qt * 16 + gid;
#pragma unroll
        for (int ct = 0; ct < 4; ct++) {
            const int t = qt * 4 + ct;
            const int lc = cw + ct * 8 + 2 * tig;
            float2 oA = make_float2(-tot[t][0], -tot[t][1]);
            float2 oB = make_float2(-tot[t][2], -tot[t][3]);
            *(float2*)(out + (size_t)(q0 + lqA) * NC + c0 + lc)     = oA;
            *(float2*)(out + (size_t)(q0 + lqA + 8) * NC + c0 + lc) = oB;
        }
    }
}

// ---------------------------------------------------------------------------
extern "C" void kernel_launch(void* const* d_in, const int* in_sizes, int n_in,
                              void* d_out, int out_size)
{
    const float* x_q  = (const float*)d_in[0];
    const float* x_c  = (const float*)d_in[1];
    const float* We   = (const float*)d_in[2];
    const float* be   = (const float*)d_in[3];
    const float* Wh   = (const float*)d_in[4];
    const float* bh   = (const float*)d_in[5];
    const float* Ws   = (const float*)d_in[6];
    const float* bs   = (const float*)d_in[7];
    const float* scl  = (const float*)d_in[8];
    const float* W1   = (const float*)d_in[9];
    const float* b1   = (const float*)d_in[10];
    const float* W2   = (const float*)d_in[11];
    const float* b2   = (const float*)d_in[12];
    float* out = (float*)d_out;

    float *cfT, *cfLo, *qfT, *qfLo, *wHi, *wLo;
    cudaGetSymbolAddress((void**)&cfT,  g_cfeatT);
    cudaGetSymbolAddress((void**)&cfLo, g_cfeatLo);
    cudaGetSymbolAddress((void**)&qfT,  g_qfeatT);
    cudaGetSymbolAddress((void**)&qfLo, g_qfeatLo);
    cudaGetSymbolAddress((void**)&wHi,  g_wHi);
    cudaGetSymbolAddress((void**)&wLo,  g_wLo);

    wsplit_kernel<<<(64 * DIN + 255) / 256, 256>>>(We, Wh, Ws, wHi, wLo);
    projmma_kernel<<<NC / 64, 128>>>(x_c, be, bh, bs, scl, wHi, wLo, cfT, cfLo, NC, 0);
    projmma_kernel<<<NQ / 64, 128>>>(x_q, be, bh, bs, scl, wHi, wLo, qfT, qfLo, NQ, 1);
    mlpq_kernel<<<NQ / 64, 256>>>(x_q, W1, b1, W2, b2, qfT);
    pair_kernel<<<dim3(NC / 128, NQ / 64), 256>>>(qfT, qfLo, cfT, cfLo, out);
}